// round 1
// baseline (speedup 1.0000x reference)
#include <cuda_runtime.h>
#include <cstdint>
#include <math.h>

// Problem dims (fixed by the reference)
#define BATCH 8
#define SQL   2048
#define SKL   2048
#define DIM   1024

// ---------------- device scratch (static allocations only) ----------------
__device__ float g_Qp[(size_t)BATCH * SQL * DIM];            // 64 MB
__device__ float g_Kp[(size_t)BATCH * SKL * DIM];            // 64 MB
__device__ float g_Vp[(size_t)BATCH * SKL * DIM];            // 64 MB
__device__ float g_S [(size_t)BATCH * SQL * SKL];            // 128 MB
__device__ float g_maskf[BATCH * SKL];
__device__ int   g_mask_mode;                                // 0=i32 1=u8 2=f32 3=bf16

// ---------------- mask dtype sniffing ----------------
// mask values are only 0/1. Encodings produce disjoint 32-bit word patterns:
//   i32 : words in {0,1}
//   u8  : packed bytes of 0/1 -> many words > 1, never 0x3F80xxxx forms
//   f32 : words in {0, 0x3F800000}
//   bf16: halfword pairs -> words in {0, 0x3F80, 0x3F800000, 0x3F803F80}
// Reading only the first 16384 bytes is safe under every interpretation.
__global__ void detect_mask_kernel(const unsigned int* __restrict__ w)
{
    __shared__ unsigned int f;
    if (threadIdx.x == 0) f = 0u;
    __syncthreads();
    unsigned int loc = 0u;
    for (int i = threadIdx.x; i < 4096; i += 256) {
        unsigned int x = w[i];
        if (x == 0x3F803F80u || x == 0x00003F80u) loc |= 8u;   // bf16 signature
        if (x == 0x3F800000u)                     loc |= 4u;   // f32 signature
        if (x > 1u)                               loc |= 2u;   // u8 signature
    }
    atomicOr(&f, loc);
    __syncthreads();
    if (threadIdx.x == 0) {
        unsigned int ff = f;
        g_mask_mode = (ff & 8u) ? 3 : (ff & 4u) ? 2 : (ff & 2u) ? 1 : 0;
    }
}

__global__ void convert_mask_kernel(const void* __restrict__ m, int n)
{
    int i = blockIdx.x * blockDim.x + threadIdx.x;
    if (i >= n) return;
    int mode = g_mask_mode;
    float v;
    if (mode == 0)      v = (float)((const int*)m)[i];
    else if (mode == 1) v = (float)((const unsigned char*)m)[i];
    else if (mode == 2) v = ((const float*)m)[i];
    else {
        unsigned short h = ((const unsigned short*)m)[i];
        v = __uint_as_float(((unsigned int)h) << 16);
    }
    g_maskf[i] = v;
}

// ---------------- 128x128x8 fp32 GEMM, 8x8 per thread ----------------
// MODE 0: C = A@B + bias                (projection)
// MODE 1: C = tanh(A@B + bias)          (V projection)
// MODE 2: C = A@B^T + maskf[z, n]       (QK^T, batched via blockIdx.z)
// MODE 3: C = A@B                       (P@V,  batched via blockIdx.z)
template <int MODE>
__global__ __launch_bounds__(256, 2)
void sgemm128(const float* __restrict__ Aall, const float* __restrict__ Ball,
              const float* __restrict__ bias, float* __restrict__ Call,
              int M, int N, int K,
              long long sA, long long sB, long long sC)
{
    __shared__ float As[8][128];
    __shared__ float Bs[8][128];

    const float* A    = Aall + (long long)blockIdx.z * sA;
    const float* Bmat = Ball + (long long)blockIdx.z * sB;
    float*       C    = Call + (long long)blockIdx.z * sC;

    const int tid = threadIdx.x;
    const int m0  = blockIdx.y * 128;
    const int n0  = blockIdx.x * 128;

    // A tile: 128 rows x 8 k-cols, one float4 per thread, store transposed.
    const int ar = tid >> 1;
    const int ak = (tid & 1) * 4;
    const float* aptr = A + (size_t)(m0 + ar) * K + ak;

    // B tile.
    constexpr bool TRANSB = (MODE == 2);
    const int br  = tid >> 1;          // NT: row within N-tile
    const int bkk = (tid & 1) * 4;     // NT: k offset
    const int bkr = tid >> 5;          // NN: k row 0..7
    const int bc  = (tid & 31) * 4;    // NN: n col (float4)
    const float* bptrT = Bmat + (size_t)(n0 + br) * K + bkk;
    const float* bptrN = Bmat + (size_t)bkr * N + n0 + bc;

    const int ty = tid >> 4;
    const int tx = tid & 15;

    float acc[8][8];
#pragma unroll
    for (int i = 0; i < 8; i++)
#pragma unroll
        for (int j = 0; j < 8; j++) acc[i][j] = 0.f;

    float4 pa = *(const float4*)(aptr);
    float4 pb = TRANSB ? *(const float4*)(bptrT) : *(const float4*)(bptrN);

    for (int kt = 0; kt < K; kt += 8) {
        __syncthreads();
        As[ak + 0][ar] = pa.x; As[ak + 1][ar] = pa.y;
        As[ak + 2][ar] = pa.z; As[ak + 3][ar] = pa.w;
        if (TRANSB) {
            Bs[bkk + 0][br] = pb.x; Bs[bkk + 1][br] = pb.y;
            Bs[bkk + 2][br] = pb.z; Bs[bkk + 3][br] = pb.w;
        } else {
            *(float4*)&Bs[bkr][bc] = pb;
        }
        __syncthreads();

        const int kn = kt + 8;
        if (kn < K) {
            pa = *(const float4*)(aptr + kn);
            pb = TRANSB ? *(const float4*)(bptrT + kn)
                        : *(const float4*)(bptrN + (size_t)kn * N);
        }

#pragma unroll
        for (int kk = 0; kk < 8; kk++) {
            float a[8], b[8];
            *(float4*)&a[0] = *(const float4*)&As[kk][ty * 8];
            *(float4*)&a[4] = *(const float4*)&As[kk][ty * 8 + 4];
            *(float4*)&b[0] = *(const float4*)&Bs[kk][tx * 8];
            *(float4*)&b[4] = *(const float4*)&Bs[kk][tx * 8 + 4];
#pragma unroll
            for (int i = 0; i < 8; i++)
#pragma unroll
                for (int j = 0; j < 8; j++)
                    acc[i][j] = fmaf(a[i], b[j], acc[i][j]);
        }
    }

    const int cm = m0 + ty * 8;
    const int cn = n0 + tx * 8;
    float bv[8];
    if (MODE == 0 || MODE == 1) {
#pragma unroll
        for (int j = 0; j < 8; j++) bv[j] = bias[cn + j];
    } else if (MODE == 2) {
#pragma unroll
        for (int j = 0; j < 8; j++) bv[j] = g_maskf[blockIdx.z * SKL + cn + j];
    } else {
#pragma unroll
        for (int j = 0; j < 8; j++) bv[j] = 0.f;
    }

#pragma unroll
    for (int i = 0; i < 8; i++) {
        float o[8];
#pragma unroll
        for (int j = 0; j < 8; j++) {
            float vv = acc[i][j] + bv[j];
            if (MODE == 1) vv = tanhf(vv);
            o[j] = vv;
        }
        float* crow = C + (size_t)(cm + i) * N + cn;
        *(float4*)&crow[0] = *(float4*)&o[0];
        *(float4*)&crow[4] = *(float4*)&o[4];
    }
}

// ---------------- row softmax over SK=2048 ----------------
__global__ __launch_bounds__(256)
void softmax_rows(float* __restrict__ S)
{
    float* row = S + (size_t)blockIdx.x * SKL;
    const int t = threadIdx.x;
    float v[8];
    float mx = -INFINITY;
#pragma unroll
    for (int i = 0; i < 8; i++) { v[i] = row[t + i * 256]; mx = fmaxf(mx, v[i]); }

    __shared__ float red[256];
    red[t] = mx; __syncthreads();
#pragma unroll
    for (int s = 128; s > 0; s >>= 1) {
        if (t < s) red[t] = fmaxf(red[t], red[t + s]);
        __syncthreads();
    }
    mx = red[0];
    __syncthreads();

    float sum = 0.f;
#pragma unroll
    for (int i = 0; i < 8; i++) { v[i] = __expf(v[i] - mx); sum += v[i]; }
    red[t] = sum; __syncthreads();
#pragma unroll
    for (int s = 128; s > 0; s >>= 1) {
        if (t < s) red[t] += red[t + s];
        __syncthreads();
    }
    const float inv = 1.0f / red[0];
#pragma unroll
    for (int i = 0; i < 8; i++) row[t + i * 256] = v[i] * inv;
}

// ---------------- launch ----------------
extern "C" void kernel_launch(void* const* d_in, const int* in_sizes, int n_in,
                              void* d_out, int out_size)
{
    const float* q    = (const float*)d_in[0];
    const float* k    = (const float*)d_in[1];
    const float* v    = (const float*)d_in[2];
    const void*  mask = d_in[3];
    const float* Wq   = (const float*)d_in[4];
    const float* bq   = (const float*)d_in[5];
    const float* Wk   = (const float*)d_in[6];
    const float* bk   = (const float*)d_in[7];
    const float* Wv   = (const float*)d_in[8];
    const float* bvp  = (const float*)d_in[9];
    float* out        = (float*)d_out;

    float *pQp, *pKp, *pVp, *pS;
    cudaGetSymbolAddress((void**)&pQp, g_Qp);
    cudaGetSymbolAddress((void**)&pKp, g_Kp);
    cudaGetSymbolAddress((void**)&pVp, g_Vp);
    cudaGetSymbolAddress((void**)&pS,  g_S);

    // mask -> float
    detect_mask_kernel<<<1, 256>>>((const unsigned int*)mask);
    convert_mask_kernel<<<(BATCH * SKL + 255) / 256, 256>>>(mask, BATCH * SKL);

    // Projections: [B*S, D] @ [D, D]
    {
        dim3 grid(DIM / 128, (BATCH * SQL) / 128, 1);
        sgemm128<0><<<grid, 256>>>(q, Wq, bq, pQp, BATCH * SQL, DIM, DIM, 0, 0, 0);
        sgemm128<0><<<grid, 256>>>(k, Wk, bk, pKp, BATCH * SKL, DIM, DIM, 0, 0, 0);
        sgemm128<1><<<grid, 256>>>(v, Wv, bvp, pVp, BATCH * SKL, DIM, DIM, 0, 0, 0);
    }

    // S = Qp @ Kp^T + mask  (batched)
    {
        dim3 grid(SKL / 128, SQL / 128, BATCH);
        sgemm128<2><<<grid, 256>>>(pQp, pKp, nullptr, pS, SQL, SKL, DIM,
                                   (long long)SQL * DIM, (long long)SKL * DIM,
                                   (long long)SQL * SKL);
    }

    // softmax rows
    softmax_rows<<<BATCH * SQL, 256>>>(pS);

    // out = P @ Vp  (batched)
    {
        dim3 grid(DIM / 128, SQL / 128, BATCH);
        sgemm128<3><<<grid, 256>>>(pS, pVp, nullptr, out, SQL, DIM, SKL,
                                   (long long)SQL * SKL, (long long)SKL * DIM,
                                   (long long)SQL * DIM);
    }
}

// round 4
// speedup vs baseline: 2.2262x; 2.2262x over previous
#include <cuda_runtime.h>
#include <cstdint>
#include <math.h>

// Problem dims
#define BATCH 8
#define SQL   2048
#define SKL   2048
#define DIM   1024

#define NELEM ((size_t)BATCH * SQL * DIM)      // 16.8M floats = 64MB

// ---------------- device scratch (static) ----------------
__device__ float g_qh[NELEM],  g_ql[NELEM];
__device__ float g_kh[NELEM],  g_kl[NELEM];
__device__ float g_vh[NELEM],  g_vl[NELEM];
__device__ float g_Wqh[DIM*DIM], g_Wql[DIM*DIM];
__device__ float g_Wkh[DIM*DIM], g_Wkl[DIM*DIM];
__device__ float g_Wvh[DIM*DIM], g_Wvl[DIM*DIM];
__device__ float g_Qph[NELEM], g_Qpl[NELEM];
__device__ float g_Kph[NELEM], g_Kpl[NELEM];
__device__ float g_Vph[NELEM], g_Vpl[NELEM];     // [B*SK][DV]
__device__ float g_S[(size_t)BATCH * SQL * SKL]; // scores, then P (tf32-rounded)
__device__ float g_maskf[BATCH * SKL];
__device__ int   g_mask_mode;

// ---------------- small helpers ----------------
__device__ __forceinline__ uint32_t smem_u32(const void* p) {
    uint32_t a;
    asm("{ .reg .u64 t; cvta.to.shared.u64 t, %1; cvt.u32.u64 %0, t; }" : "=r"(a) : "l"(p));
    return a;
}
__device__ __forceinline__ float tf32_rna(float x) {
    uint32_t u;
    asm("cvt.rna.tf32.f32 %0, %1;" : "=r"(u) : "f"(x));
    return __uint_as_float(u);
}
__device__ __forceinline__ void cp16(uint32_t dst, const void* src) {
    asm volatile("cp.async.cg.shared.global [%0], [%1], 16;" :: "r"(dst), "l"(src) : "memory");
}
__device__ __forceinline__ void cp_commit() {
    asm volatile("cp.async.commit_group;" ::: "memory");
}
template<int N> __device__ __forceinline__ void cp_wait() {
    asm volatile("cp.async.wait_group %0;" :: "n"(N) : "memory");
}
// mma.sync m16n8k8 tf32 (base PTX, runs on sm_103 fallback path)
__device__ __forceinline__ void mma8(float* c, const uint32_t* a, const uint32_t* b) {
    asm volatile(
        "mma.sync.aligned.m16n8k8.row.col.f32.tf32.tf32.f32 "
        "{%0,%1,%2,%3}, {%4,%5,%6,%7}, {%8,%9}, {%0,%1,%2,%3};"
        : "+f"(c[0]), "+f"(c[1]), "+f"(c[2]), "+f"(c[3])
        : "r"(a[0]), "r"(a[1]), "r"(a[2]), "r"(a[3]), "r"(b[0]), "r"(b[1]));
}
// swizzled K-major tile load: tile [128 rows][32 floats], 16B chunk swizzle c ^= (r&7)
__device__ __forceinline__ uint32_t sw_ld(const float* t, int r, int k) {
    return __float_as_uint(t[r * 32 + ((((k >> 2) ^ r) & 7) << 2) + (k & 3)]);
}

// ---------------- mask dtype sniffing (verified R1) ----------------
__global__ void detect_mask_kernel(const unsigned int* __restrict__ w)
{
    __shared__ unsigned int f;
    if (threadIdx.x == 0) f = 0u;
    __syncthreads();
    unsigned int loc = 0u;
    for (int i = threadIdx.x; i < 4096; i += 256) {
        unsigned int x = w[i];
        if (x == 0x3F803F80u || x == 0x00003F80u) loc |= 8u;
        if (x == 0x3F800000u)                     loc |= 4u;
        if (x > 1u)                               loc |= 2u;
    }
    atomicOr(&f, loc);
    __syncthreads();
    if (threadIdx.x == 0) {
        unsigned int ff = f;
        g_mask_mode = (ff & 8u) ? 3 : (ff & 4u) ? 2 : (ff & 2u) ? 1 : 0;
    }
}
__global__ void convert_mask_kernel(const void* __restrict__ m, int n)
{
    int i = blockIdx.x * blockDim.x + threadIdx.x;
    if (i >= n) return;
    int mode = g_mask_mode;
    float v;
    if (mode == 0)      v = (float)((const int*)m)[i];
    else if (mode == 1) v = (float)((const unsigned char*)m)[i];
    else if (mode == 2) v = ((const float*)m)[i];
    else {
        unsigned short h = ((const unsigned short*)m)[i];
        v = __uint_as_float(((unsigned int)h) << 16);
    }
    g_maskf[i] = v;
}

// ---------------- tf32 hi/lo splits ----------------
__global__ __launch_bounds__(256)
void split_kernel(const float4* __restrict__ src, float4* __restrict__ hi,
                  float4* __restrict__ lo, int n4)
{
    int i = blockIdx.x * blockDim.x + threadIdx.x;
    if (i >= n4) return;
    float4 x = src[i];
    float4 h, l;
    h.x = tf32_rna(x.x); l.x = x.x - h.x;
    h.y = tf32_rna(x.y); l.y = x.y - h.y;
    h.z = tf32_rna(x.z); l.z = x.z - h.z;
    h.w = tf32_rna(x.w); l.w = x.w - h.w;
    hi[i] = h; lo[i] = l;
}

// W [K=1024, N=1024] -> WT_hi/lo [N, K]
__global__ __launch_bounds__(256)
void transpose_split_kernel(const float* __restrict__ W,
                            float* __restrict__ Th, float* __restrict__ Tl)
{
    __shared__ float t[32][33];
    int n0 = blockIdx.x * 32, k0 = blockIdx.y * 32;
    int tx = threadIdx.x & 31, ty = threadIdx.x >> 5;
    for (int r = ty; r < 32; r += 8)
        t[r][tx] = W[(size_t)(k0 + r) * DIM + n0 + tx];
    __syncthreads();
    for (int r = ty; r < 32; r += 8) {
        float x = t[tx][r];
        float h = tf32_rna(x);
        size_t o = (size_t)(n0 + r) * DIM + k0 + tx;
        Th[o] = h; Tl[o] = x - h;
    }
}

// ---------------- mma.sync tf32 GEMM: 128x128 tile, Kc=32, 3-stage cp.async --------
// MODE 0: C = A@B^T + bias      -> split hi/lo write     (Q/K projection)
// MODE 1: C = tanh(A@B^T+bias)  -> split hi/lo write     (V projection)
// MODE 2: C = A@B^T + mask      -> f32 write             (QK^T)
// MODE 3: C = A@B  (B=[K][N])   -> f32 write             (P@V, 2-product)
// Products: modes 0-2: Ah*Bh + Ah*Bl + Al*Bh (3xTF32); mode 3: A*Bh + A*Bl.
#define STG0_FL 16384                 // per-stage floats modes 0-2 (4 tiles x 4096)
#define STG3_FL (4096 + 2*32*136)     // mode 3: A tile + 2 x [32][136] B tiles

template<int MODE>
__global__ __launch_bounds__(256, 1)
void mma_gemm(const float* __restrict__ Ah, const float* __restrict__ Al,
              const float* __restrict__ Bh, const float* __restrict__ Bl,
              const float* __restrict__ aux,
              float* __restrict__ out0, float* __restrict__ out1,
              int ldA, int ldB, long long sAz, long long sBz,
              int nK, int ldO, long long sOz)
{
    constexpr bool SA = (MODE != 3);
    constexpr bool BK = (MODE == 3);
    constexpr int  STG = SA ? STG0_FL : STG3_FL;

    extern __shared__ float sm[];
    const uint32_t sb = smem_u32(sm);
    const int tid = threadIdx.x;
    const int lid = tid & 31, wid = tid >> 5;
    const int wm = wid >> 2, wn = wid & 3;      // 2 x 4 warp grid
    const int lx = lid & 3,  ly = lid >> 2;
    const int m0 = blockIdx.y * 128, n0 = blockIdx.x * 128, z = blockIdx.z;
    const int nst = nK / 32;

    const float* Agh = Ah + (size_t)z * sAz;
    const float* Agl = SA ? (Al + (size_t)z * sAz) : Ah;
    const float* Bgh = Bh + (size_t)z * sBz;
    const float* Bgl = Bl + (size_t)z * sBz;

    float acc[4][4][4];
#pragma unroll
    for (int a = 0; a < 4; a++)
#pragma unroll
        for (int b = 0; b < 4; b++)
#pragma unroll
            for (int c = 0; c < 4; c++) acc[a][b][c] = 0.f;

    // ---- producer: fills stage SLOT st (0..2) with k-chunk kt ----
    auto issue = [&](int st, int kt) {
        uint32_t base = sb + (uint32_t)st * STG * 4;
#pragma unroll
        for (int i = 0; i < 4; i++) {
            int q = i * 256 + tid; int r = q >> 3, c = q & 7;
            uint32_t d = (uint32_t)(r * 128 + ((c ^ (r & 7)) << 4));
            cp16(base + d, Agh + (size_t)(m0 + r) * ldA + kt + c * 4);
            if (SA) cp16(base + 4096 * 4 + d, Agl + (size_t)(m0 + r) * ldA + kt + c * 4);
        }
        uint32_t bb = base + (SA ? 8192u * 4 : 4096u * 4);
        if (!BK) {
#pragma unroll
            for (int i = 0; i < 4; i++) {
                int q = i * 256 + tid; int r = q >> 3, c = q & 7;
                uint32_t d = (uint32_t)(r * 128 + ((c ^ (r & 7)) << 4));
                cp16(bb + d,            Bgh + (size_t)(n0 + r) * ldB + kt + c * 4);
                cp16(bb + 4096 * 4 + d, Bgl + (size_t)(n0 + r) * ldB + kt + c * 4);
            }
        } else {
#pragma unroll
            for (int i = 0; i < 4; i++) {
                int q = i * 256 + tid; int r = q >> 5, c = q & 31;
                uint32_t d = (uint32_t)(r * 544 + c * 16);
                cp16(bb + d,            Bgh + (size_t)(kt + r) * ldB + n0 + c * 4);
                cp16(bb + 4352 * 4 + d, Bgl + (size_t)(kt + r) * ldB + n0 + c * 4);
            }
        }
        cp_commit();
    };

    issue(0, 0); issue(1, 32); issue(2, 64);

#pragma unroll 1
    for (int it = 0; it < nst; it++) {
        // tail-aware drain: guarantee group `it` is complete
        if (it + 2 < nst)      cp_wait<2>();
        else if (it + 1 < nst) cp_wait<1>();
        else                   cp_wait<0>();
        __syncthreads();
        const float* S0  = sm + (it % 3) * STG;
        const float* SAh = S0;
        const float* SAl = S0 + 4096;
        const float* SBh = S0 + (SA ? 8192 : 4096);
        const float* SBl = SBh + (SA ? 4096 : 4352);

#pragma unroll
        for (int ks = 0; ks < 4; ks++) {
            const int k0 = ks * 8;
            uint32_t ah[4][4];
#pragma unroll
            for (int mt = 0; mt < 4; mt++) {
                int rm = wm * 64 + mt * 16 + ly;
                ah[mt][0] = sw_ld(SAh, rm,     k0 + lx);
                ah[mt][1] = sw_ld(SAh, rm + 8, k0 + lx);
                ah[mt][2] = sw_ld(SAh, rm,     k0 + 4 + lx);
                ah[mt][3] = sw_ld(SAh, rm + 8, k0 + 4 + lx);
            }
            uint32_t bh[4][2], bl[4][2];
#pragma unroll
            for (int nt = 0; nt < 4; nt++) {
                int cn = wn * 32 + nt * 8 + ly;
                if (!BK) {
                    bh[nt][0] = sw_ld(SBh, cn, k0 + lx);
                    bh[nt][1] = sw_ld(SBh, cn, k0 + 4 + lx);
                    bl[nt][0] = sw_ld(SBl, cn, k0 + lx);
                    bl[nt][1] = sw_ld(SBl, cn, k0 + 4 + lx);
                } else {
                    bh[nt][0] = __float_as_uint(SBh[(k0 + lx) * 136 + cn]);
                    bh[nt][1] = __float_as_uint(SBh[(k0 + 4 + lx) * 136 + cn]);
                    bl[nt][0] = __float_as_uint(SBl[(k0 + lx) * 136 + cn]);
                    bl[nt][1] = __float_as_uint(SBl[(k0 + 4 + lx) * 136 + cn]);
                }
            }
#pragma unroll
            for (int mt = 0; mt < 4; mt++)
#pragma unroll
                for (int nt = 0; nt < 4; nt++) {
                    mma8(acc[mt][nt], ah[mt], bh[nt]);
                    mma8(acc[mt][nt], ah[mt], bl[nt]);
                }
            if (SA) {
                uint32_t alr[4][4];
#pragma unroll
                for (int mt = 0; mt < 4; mt++) {
                    int rm = wm * 64 + mt * 16 + ly;
                    alr[mt][0] = sw_ld(SAl, rm,     k0 + lx);
                    alr[mt][1] = sw_ld(SAl, rm + 8, k0 + lx);
                    alr[mt][2] = sw_ld(SAl, rm,     k0 + 4 + lx);
                    alr[mt][3] = sw_ld(SAl, rm + 8, k0 + 4 + lx);
                }
#pragma unroll
                for (int mt = 0; mt < 4; mt++)
#pragma unroll
                    for (int nt = 0; nt < 4; nt++)
                        mma8(acc[mt][nt], alr[mt], bh[nt]);
            }
        }
        __syncthreads();
        // refill the slot just consumed (slot it%3) with chunk it+3
        if (it + 3 < nst) issue(it % 3, (it + 3) * 32);
    }

    // ---- epilogue ----
#pragma unroll
    for (int mt = 0; mt < 4; mt++) {
#pragma unroll
        for (int hf = 0; hf < 2; hf++) {
            const int gm = m0 + wm * 64 + mt * 16 + ly + hf * 8;
#pragma unroll
            for (int nt = 0; nt < 4; nt++) {
                const int col = n0 + wn * 32 + nt * 8 + 2 * lx;
                float c0 = acc[mt][nt][hf * 2 + 0];
                float c1 = acc[mt][nt][hf * 2 + 1];
                if (MODE == 0 || MODE == 1) {
                    float x0 = c0 + aux[col], x1 = c1 + aux[col + 1];
                    if (MODE == 1) { x0 = tanhf(x0); x1 = tanhf(x1); }
                    float h0 = tf32_rna(x0), h1 = tf32_rna(x1);
                    float2* p0 = (float2*)(out0 + (size_t)gm * ldO + col);
                    float2* p1 = (float2*)(out1 + (size_t)gm * ldO + col);
                    *p0 = make_float2(h0, h1);
                    *p1 = make_float2(x0 - h0, x1 - h1);
                } else if (MODE == 2) {
                    float x0 = c0 + aux[(size_t)z * SKL + col];
                    float x1 = c1 + aux[(size_t)z * SKL + col + 1];
                    *(float2*)(out0 + (size_t)z * sOz + (size_t)gm * ldO + col) =
                        make_float2(x0, x1);
                } else {
                    *(float2*)(out0 + (size_t)z * sOz + (size_t)gm * ldO + col) =
                        make_float2(c0, c1);
                }
            }
        }
    }
}

// ---------------- softmax (in place, writes tf32-rounded P) ----------------
__global__ __launch_bounds__(256)
void softmax_rows(float* __restrict__ S)
{
    float* row = S + (size_t)blockIdx.x * SKL;
    const int t = threadIdx.x;
    float v[8];
    float mx = -INFINITY;
#pragma unroll
    for (int i = 0; i < 8; i++) { v[i] = row[t + i * 256]; mx = fmaxf(mx, v[i]); }

    __shared__ float red[256];
    red[t] = mx; __syncthreads();
#pragma unroll
    for (int s = 128; s > 0; s >>= 1) {
        if (t < s) red[t] = fmaxf(red[t], red[t + s]);
        __syncthreads();
    }
    mx = red[0];
    __syncthreads();

    float sum = 0.f;
#pragma unroll
    for (int i = 0; i < 8; i++) { v[i] = __expf(v[i] - mx); sum += v[i]; }
    red[t] = sum; __syncthreads();
#pragma unroll
    for (int s = 128; s > 0; s >>= 1) {
        if (t < s) red[t] += red[t + s];
        __syncthreads();
    }
    const float inv = 1.0f / red[0];
#pragma unroll
    for (int i = 0; i < 8; i++) row[t + i * 256] = tf32_rna(v[i] * inv);
}

// ---------------- launch ----------------
extern "C" void kernel_launch(void* const* d_in, const int* in_sizes, int n_in,
                              void* d_out, int out_size)
{
    const float* q    = (const float*)d_in[0];
    const float* k    = (const float*)d_in[1];
    const float* v    = (const float*)d_in[2];
    const void*  mask = d_in[3];
    const float* Wq   = (const float*)d_in[4];
    const float* bq   = (const float*)d_in[5];
    const float* Wk   = (const float*)d_in[6];
    const float* bk   = (const float*)d_in[7];
    const float* Wv   = (const float*)d_in[8];
    const float* bvp  = (const float*)d_in[9];
    float* out        = (float*)d_out;

    float *qh, *ql, *kh, *kl, *vh, *vl, *Wqh, *Wql, *Wkh, *Wkl, *Wvh, *Wvl;
    float *Qph, *Qpl, *Kph, *Kpl, *Vph, *Vpl, *S, *maskf;
    cudaGetSymbolAddress((void**)&qh, g_qh);   cudaGetSymbolAddress((void**)&ql, g_ql);
    cudaGetSymbolAddress((void**)&kh, g_kh);   cudaGetSymbolAddress((void**)&kl, g_kl);
    cudaGetSymbolAddress((void**)&vh, g_vh);   cudaGetSymbolAddress((void**)&vl, g_vl);
    cudaGetSymbolAddress((void**)&Wqh, g_Wqh); cudaGetSymbolAddress((void**)&Wql, g_Wql);
    cudaGetSymbolAddress((void**)&Wkh, g_Wkh); cudaGetSymbolAddress((void**)&Wkl, g_Wkl);
    cudaGetSymbolAddress((void**)&Wvh, g_Wvh); cudaGetSymbolAddress((void**)&Wvl, g_Wvl);
    cudaGetSymbolAddress((void**)&Qph, g_Qph); cudaGetSymbolAddress((void**)&Qpl, g_Qpl);
    cudaGetSymbolAddress((void**)&Kph, g_Kph); cudaGetSymbolAddress((void**)&Kpl, g_Kpl);
    cudaGetSymbolAddress((void**)&Vph, g_Vph); cudaGetSymbolAddress((void**)&Vpl, g_Vpl);
    cudaGetSymbolAddress((void**)&S, g_S);     cudaGetSymbolAddress((void**)&maskf, g_maskf);

    // mask -> float
    detect_mask_kernel<<<1, 256>>>((const unsigned int*)mask);
    convert_mask_kernel<<<(BATCH * SKL + 255) / 256, 256>>>(mask, BATCH * SKL);

    // split inputs q,k,v into tf32 hi/lo
    {
        int n4 = (int)(NELEM / 4);
        int nb = (n4 + 255) / 256;
        split_kernel<<<nb, 256>>>((const float4*)q, (float4*)qh, (float4*)ql, n4);
        split_kernel<<<nb, 256>>>((const float4*)k, (float4*)kh, (float4*)kl, n4);
        split_kernel<<<nb, 256>>>((const float4*)v, (float4*)vh, (float4*)vl, n4);
    }
    // transpose + split weights -> [N][K]
    {
        dim3 g(DIM / 32, DIM / 32);
        transpose_split_kernel<<<g, 256>>>(Wq, Wqh, Wql);
        transpose_split_kernel<<<g, 256>>>(Wk, Wkh, Wkl);
        transpose_split_kernel<<<g, 256>>>(Wv, Wvh, Wvl);
    }

    const int SMEM0 = 3 * STG0_FL * 4;   // 196608 B
    const int SMEM3 = 3 * STG3_FL * 4;   // 153600 B
    cudaFuncSetAttribute(mma_gemm<0>, cudaFuncAttributeMaxDynamicSharedMemorySize, SMEM0);
    cudaFuncSetAttribute(mma_gemm<1>, cudaFuncAttributeMaxDynamicSharedMemorySize, SMEM0);
    cudaFuncSetAttribute(mma_gemm<2>, cudaFuncAttributeMaxDynamicSharedMemorySize, SMEM0);
    cudaFuncSetAttribute(mma_gemm<3>, cudaFuncAttributeMaxDynamicSharedMemorySize, SMEM3);

    // Projections: M = B*SQL = 16384 rows, N = 1024
    {
        dim3 grid(DIM / 128, (BATCH * SQL) / 128, 1);
        mma_gemm<0><<<grid, 256, SMEM0>>>(qh, ql, Wqh, Wql, bq, Qph, Qpl,
                                          DIM, DIM, 0, 0, DIM, DIM, 0);
        mma_gemm<0><<<grid, 256, SMEM0>>>(kh, kl, Wkh, Wkl, bk, Kph, Kpl,
                                          DIM, DIM, 0, 0, DIM, DIM, 0);
        mma_gemm<1><<<grid, 256, SMEM0>>>(vh, vl, Wvh, Wvl, bvp, Vph, Vpl,
                                          DIM, DIM, 0, 0, DIM, DIM, 0);
    }

    // S = Qp @ Kp^T + mask (batched)
    {
        dim3 grid(SKL / 128, SQL / 128, BATCH);
        mma_gemm<2><<<grid, 256, SMEM0>>>(Qph, Qpl, Kph, Kpl, maskf, S, nullptr,
                                          DIM, DIM, (long long)SQL * DIM,
                                          (long long)SKL * DIM, DIM, SKL,
                                          (long long)SQL * SKL);
    }

    // softmax rows (writes tf32-rounded P in place)
    softmax_rows<<<BATCH * SQL, 256>>>(S);

    // out = P @ Vp (batched, B stored [K=sk][N=dv])
    {
        dim3 grid(DIM / 128, SQL / 128, BATCH);
        mma_gemm<3><<<grid, 256, SMEM3>>>(S, nullptr, Vph, Vpl, nullptr, out, nullptr,
                                          SKL, DIM, (long long)SQL * SKL,
                                          (long long)SKL * DIM, SKL, DIM,
                                          (long long)SQL * DIM);
    }
}